// round 13
// baseline (speedup 1.0000x reference)
#include <cuda_runtime.h>

typedef unsigned long long u64;

#define RAD 4
#define P 2                      // output rows per thread
#define BW 32                    // threads in x (each does 2 px)
#define BY 16                    // threads in y
#define NTHREADS (BW * BY)       // 512
#define TX (BW * 2)              // 64
#define TY (BY * P)              // 32
#define HALO_W (TX + 2 * RAD)    // 72
#define HALO_H (TY + 2 * RAD)    // 40
#define PITCH  HALO_W
#define PLANE  (HALO_H * PITCH)  // 2880 floats
#define SMEM_BYTES (6 * PLANE * 4)  // 69120 B (dynamic)
#define IMG_H 1024
#define IMG_W 1024
#define IMG_B 8
#define TILES_X (IMG_W / TX)     // 16
#define TILES_Y (IMG_H / TY)     // 32
#define NTILES  (TILES_X * TILES_Y * IMG_B)  // 4096

// C1 = (-0.5 / (75*75)) * log2(e)  — shared by color and space terms
#define C1F  (-1.2823955919013e-04f)
// KS = sqrt(-C1): pre-scale pixels so (scaled diff-sum)^2 == -C1 * s^2
#define KS   (1.1324291e-02f)
#define IKS  (88.3047182986f)    // 1/KS, folded into the final reciprocal

__device__ __forceinline__ u64 f2add(u64 a, u64 b) {
    u64 r; asm("add.rn.f32x2 %0, %1, %2;" : "=l"(r) : "l"(a), "l"(b)); return r;
}
__device__ __forceinline__ u64 f2sub(u64 a, u64 b) {
    u64 r; asm("sub.rn.f32x2 %0, %1, %2;" : "=l"(r) : "l"(a), "l"(b)); return r;
}
__device__ __forceinline__ u64 f2fma(u64 a, u64 b, u64 c) {
    u64 r; asm("fma.rn.f32x2 %0, %1, %2, %3;" : "=l"(r) : "l"(a), "l"(b), "l"(c)); return r;
}
__device__ __forceinline__ float2 f2unpack(u64 v) {
    float2 r; asm("mov.b64 {%0, %1}, %2;" : "=f"(r.x), "=f"(r.y) : "l"(v)); return r;
}
// two scalar log-weights -> packed pair of ex2 results, single asm block
__device__ __forceinline__ u64 f2ex2s(float a, float b) {
    u64 r;
    asm("{\n\t"
        ".reg .b32 x, y;\n\t"
        "ex2.approx.f32 x, %1;\n\t"
        "ex2.approx.f32 y, %2;\n\t"
        "mov.b64 %0, {x, y};\n\t"
        "}" : "=l"(r) : "f"(a), "f"(b));
    return r;
}
__device__ __forceinline__ float frcp(float x) {
    float r; asm("rcp.approx.f32 %0, %1;" : "=f"(r) : "f"(x)); return r;
}
__device__ __forceinline__ int refl(int i, int n) {
    if (i < 0) i = -i;
    if (i >= n) i = 2 * n - 2 - i;
    return i;
}

__global__ void __launch_bounds__(NTHREADS, 2)
bilateral_kernel(const float* __restrict__ in, float* __restrict__ out)
{
    // planes 0..2: r,g,b aligned copies; planes 3..5: shifted-by-one copies
    // (odd[j] = V[j+1]) so odd-dx pixel pairs are 8B-aligned LDS.64 too.
    // All values pre-scaled by KS. Dynamic smem: 69120 B.
    extern __shared__ __align__(16) float sm[];

    // thread-invariant across tiles: smem base pointer for this thread
    const int clx   = RAD + 2 * threadIdx.x;   // even
    const int crow0 = RAD + threadIdx.y * P;
    const float* pb = sm + crow0 * PITCH + clx;
    const u64 one2 = 0x3F8000003F800000ULL;    // packed {1.0f, 1.0f}

    // ---- persistent loop over tiles ----
    for (int t = blockIdx.x; t < NTILES; t += gridDim.x) {
        const int bx = t & (TILES_X - 1);
        const int by = (t >> 4) & (TILES_Y - 1);
        const int b  = t >> 9;
        const int x0 = bx * TX;
        const int y0 = by * TY;
        const float* img = in + (size_t)b * ((size_t)IMG_H * IMG_W * 3);

        __syncthreads();   // previous tile's readers done before overwriting smem

        // ---- cooperative halo load (reflect padding), deinterleave ----
        for (int lr = threadIdx.y; lr < HALO_H; lr += BY) {
            int gy = refl(y0 + lr - RAD, IMG_H);
            const float* rowp = img + (size_t)gy * (IMG_W * 3);
            for (int lx = threadIdx.x; lx < HALO_W; lx += BW) {
                int gx = refl(x0 + lx - RAD, IMG_W);
                const float* p = rowp + gx * 3;
                float vr = p[0] * KS, vg = p[1] * KS, vb = p[2] * KS;
                int e = lr * PITCH + lx;
                sm[0 * PLANE + e] = vr;
                sm[1 * PLANE + e] = vg;
                sm[2 * PLANE + e] = vb;
                if (lx > 0) {
                    sm[3 * PLANE + e - 1] = vr;
                    sm[4 * PLANE + e - 1] = vg;
                    sm[5 * PLANE + e - 1] = vb;
                }
            }
        }
        __syncthreads();

        // ---- per-thread: 2 adjacent pixels (f32x2) x P stacked rows ----
        u64 cr[P], cg[P], cb[P];
        u64 ar[P], ag[P], ab[P], ad[P];
#pragma unroll
        for (int p = 0; p < P; ++p) {
            cr[p] = *(const u64*)(pb + p * PITCH + 0 * PLANE);
            cg[p] = *(const u64*)(pb + p * PITCH + 1 * PLANE);
            cb[p] = *(const u64*)(pb + p * PITCH + 2 * PLANE);
            ar[p] = 0ULL; ag[p] = 0ULL; ab[p] = 0ULL; ad[p] = 0ULL;
        }

#pragma unroll
        for (int dx = -RAD; dx <= RAD; ++dx) {
            const int adx = dx < 0 ? -dx : dx;
            const int dyM = (adx == 0) ? 4 : (adx <= 2) ? 3 : (adx == 3) ? 2 : 0;
            const int pl  = (dx & 1) ? 3 : 0;
            const int cof = (dx & 1) ? dx - 1 : dx;
#pragma unroll
            for (int ry = -dyM; ry <= P - 1 + dyM; ++ry) {
                const int off = ry * PITCH + cof;
                const u64 nr = *(const u64*)(pb + (pl + 0) * PLANE + off);
                const u64 ng = *(const u64*)(pb + (pl + 1) * PLANE + off);
                const u64 nb = *(const u64*)(pb + (pl + 2) * PLANE + off);
#pragma unroll
                for (int p = 0; p < P; ++p) {
                    const int dy = ry - p;
                    if (dy < -dyM || dy > dyM) continue;   // circular mask
                    if (dx == 0 && dy == 0) {
                        // center tap: w == 1 exactly
                        ar[p] = f2add(ar[p], nr);
                        ag[p] = f2add(ag[p], ng);
                        ab[p] = f2add(ab[p], nb);
                        ad[p] = f2add(ad[p], one2);
                        continue;
                    }
                    const int r2 = dy * dy + dx * dx;
                    const float lsw = C1F * (float)r2;     // log2 spatial w

                    // packed diffs, scalar abs-sums (FADD folds |src| free).
                    // Pre-scaled data: log2(w) = -(s*s) + lsw : ONE FFMA.
                    float2 drf = f2unpack(f2sub(nr, cr[p]));
                    float2 dgf = f2unpack(f2sub(ng, cg[p]));
                    float2 dbf = f2unpack(f2sub(nb, cb[p]));
                    float s0 = fabsf(drf.x) + fabsf(dgf.x);
                    float s1 = fabsf(drf.y) + fabsf(dgf.y);
                    s0 += fabsf(dbf.x);
                    s1 += fabsf(dbf.y);
                    u64 w = f2ex2s(fmaf(s0, -s0, lsw), fmaf(s1, -s1, lsw));

                    ar[p] = f2fma(w, nr, ar[p]);
                    ag[p] = f2fma(w, ng, ag[p]);
                    ab[p] = f2fma(w, nb, ab[p]);
                    ad[p] = f2add(ad[p], w);
                }
            }
        }

        // ---- write out: 6 contiguous floats/row, 8B-aligned (gx even) ----
        const int gx = x0 + 2 * threadIdx.x;
#pragma unroll
        for (int p = 0; p < P; ++p) {
            const int gy = y0 + threadIdx.y * P + p;
            float2 R = f2unpack(ar[p]), G = f2unpack(ag[p]);
            float2 B = f2unpack(ab[p]), D = f2unpack(ad[p]);
            float i0 = frcp(D.x) * IKS, i1 = frcp(D.y) * IKS;
            float* o = out + (((size_t)b * IMG_H + gy) * (size_t)IMG_W + gx) * 3;
            ((float2*)o)[0] = make_float2(R.x * i0, G.x * i0);
            ((float2*)o)[1] = make_float2(B.x * i0, R.y * i1);
            ((float2*)o)[2] = make_float2(G.y * i1, B.y * i1);
        }
    }
}

extern "C" void kernel_launch(void* const* d_in, const int* in_sizes, int n_in,
                              void* d_out, int out_size)
{
    (void)in_sizes; (void)n_in; (void)out_size;
    const float* in = (const float*)d_in[0];
    float* out = (float*)d_out;
    cudaFuncSetAttribute(bilateral_kernel,
                         cudaFuncAttributeMaxDynamicSharedMemorySize, SMEM_BYTES);
    int dev = 0, nsm = 148;
    cudaGetDevice(&dev);
    cudaDeviceGetAttribute(&nsm, cudaDevAttrMultiProcessorCount, dev);
    int nblocks = 2 * nsm;             // persistent: 2 resident CTAs per SM
    if (nblocks > NTILES) nblocks = NTILES;
    dim3 block(BW, BY);
    bilateral_kernel<<<nblocks, block, SMEM_BYTES>>>(in, out);
}

// round 14
// speedup vs baseline: 1.2246x; 1.2246x over previous
#include <cuda_runtime.h>

typedef unsigned long long u64;

#define RAD 4
#define P 2                      // output rows per thread
#define BW 32                    // threads in x (each does 2 px)
#define BY 16                    // threads in y
#define NTHREADS (BW * BY)       // 512
#define TX (BW * 2)              // 64
#define TY (BY * P)              // 32
#define HALO_W (TX + 2 * RAD)    // 72
#define HALO_H (TY + 2 * RAD)    // 40
#define PITCH  HALO_W
#define PLANE  (HALO_H * PITCH)  // 2880 floats
#define SMEM_BYTES (6 * PLANE * 4)  // 69120 B (dynamic)
#define IMG_H 1024
#define IMG_W 1024
#define IMG_B 8

// C1 = (-0.5 / (75*75)) * log2(e)  — shared by color and space terms
#define C1F  (-1.2823955919013e-04f)
// KS = sqrt(-C1): pre-scale pixels so (scaled diff-sum)^2 == -C1 * s^2
#define KS   (1.1324291e-02f)
#define IKS  (88.3047182986f)    // 1/KS, folded into the final reciprocal

__device__ __forceinline__ u64 f2add(u64 a, u64 b) {
    u64 r; asm("add.rn.f32x2 %0, %1, %2;" : "=l"(r) : "l"(a), "l"(b)); return r;
}
__device__ __forceinline__ u64 f2sub(u64 a, u64 b) {
    u64 r; asm("sub.rn.f32x2 %0, %1, %2;" : "=l"(r) : "l"(a), "l"(b)); return r;
}
__device__ __forceinline__ u64 f2fma(u64 a, u64 b, u64 c) {
    u64 r; asm("fma.rn.f32x2 %0, %1, %2, %3;" : "=l"(r) : "l"(a), "l"(b), "l"(c)); return r;
}
__device__ __forceinline__ float2 f2unpack(u64 v) {
    float2 r; asm("mov.b64 {%0, %1}, %2;" : "=f"(r.x), "=f"(r.y) : "l"(v)); return r;
}
// two scalar log-weights -> packed pair of ex2 results, single asm block
__device__ __forceinline__ u64 f2ex2s(float a, float b) {
    u64 r;
    asm("{\n\t"
        ".reg .b32 x, y;\n\t"
        "ex2.approx.f32 x, %1;\n\t"
        "ex2.approx.f32 y, %2;\n\t"
        "mov.b64 %0, {x, y};\n\t"
        "}" : "=l"(r) : "f"(a), "f"(b));
    return r;
}
__device__ __forceinline__ float frcp(float x) {
    float r; asm("rcp.approx.f32 %0, %1;" : "=f"(r) : "f"(x)); return r;
}
__device__ __forceinline__ int refl(int i, int n) {
    if (i < 0) i = -i;
    if (i >= n) i = 2 * n - 2 - i;
    return i;
}

__global__ void __launch_bounds__(NTHREADS, 2)
bilateral_kernel(const float* __restrict__ in, float* __restrict__ out)
{
    // planes 0..2: r,g,b aligned copies; planes 3..5: shifted-by-one copies
    // (odd[j] = V[j+1]) so odd-dx pixel pairs are 8B-aligned LDS.64 too.
    // All values pre-scaled by KS. Dynamic smem: 69120 B.
    extern __shared__ __align__(16) float sm[];

    const int b  = blockIdx.z;
    const int x0 = blockIdx.x * TX;
    const int y0 = blockIdx.y * TY;
    const float* img = in + (size_t)b * ((size_t)IMG_H * IMG_W * 3);

    // ---- cooperative halo load (reflect padding), deinterleave to planes ----
    // 2D strided loop: no integer division, minimal prologue code.
    for (int lr = threadIdx.y; lr < HALO_H; lr += BY) {
        int gy = refl(y0 + lr - RAD, IMG_H);
        const float* rowp = img + (size_t)gy * (IMG_W * 3);
        for (int lx = threadIdx.x; lx < HALO_W; lx += BW) {
            int gx = refl(x0 + lx - RAD, IMG_W);
            const float* p = rowp + gx * 3;
            float vr = p[0] * KS, vg = p[1] * KS, vb = p[2] * KS;
            int e = lr * PITCH + lx;
            sm[0 * PLANE + e] = vr;
            sm[1 * PLANE + e] = vg;
            sm[2 * PLANE + e] = vb;
            if (lx > 0) {
                sm[3 * PLANE + e - 1] = vr;
                sm[4 * PLANE + e - 1] = vg;
                sm[5 * PLANE + e - 1] = vb;
            }
        }
    }
    __syncthreads();

    // ---- per-thread: 2 adjacent pixels (f32x2) x P stacked rows ----
    const int clx   = RAD + 2 * threadIdx.x;   // even
    const int crow0 = RAD + threadIdx.y * P;
    const float* pb = sm + crow0 * PITCH + clx;
    const u64 one2 = 0x3F8000003F800000ULL;    // packed {1.0f, 1.0f}

    u64 cr[P], cg[P], cb[P];
    u64 ar[P], ag[P], ab[P], ad[P];
#pragma unroll
    for (int p = 0; p < P; ++p) {
        cr[p] = *(const u64*)(pb + p * PITCH + 0 * PLANE);
        cg[p] = *(const u64*)(pb + p * PITCH + 1 * PLANE);
        cb[p] = *(const u64*)(pb + p * PITCH + 2 * PLANE);
        ar[p] = 0ULL; ag[p] = 0ULL; ab[p] = 0ULL; ad[p] = 0ULL;
    }

#pragma unroll
    for (int dx = -RAD; dx <= RAD; ++dx) {
        const int adx = dx < 0 ? -dx : dx;
        const int dyM = (adx == 0) ? 4 : (adx <= 2) ? 3 : (adx == 3) ? 2 : 0;
        const int pl  = (dx & 1) ? 3 : 0;
        const int cof = (dx & 1) ? dx - 1 : dx;
#pragma unroll
        for (int ry = -dyM; ry <= P - 1 + dyM; ++ry) {
            const int off = ry * PITCH + cof;
            const u64 nr = *(const u64*)(pb + (pl + 0) * PLANE + off);
            const u64 ng = *(const u64*)(pb + (pl + 1) * PLANE + off);
            const u64 nb = *(const u64*)(pb + (pl + 2) * PLANE + off);
#pragma unroll
            for (int p = 0; p < P; ++p) {
                const int dy = ry - p;
                if (dy < -dyM || dy > dyM) continue;   // circular mask via dyM
                if (dx == 0 && dy == 0) {
                    // center tap: w == 1 exactly (nr==cr etc.)
                    ar[p] = f2add(ar[p], nr);
                    ag[p] = f2add(ag[p], ng);
                    ab[p] = f2add(ab[p], nb);
                    ad[p] = f2add(ad[p], one2);
                    continue;
                }
                const int r2 = dy * dy + dx * dx;
                const float lsw = C1F * (float)r2;     // log2 of spatial weight

                // packed diffs, scalar abs-sums (FADD folds |src| free).
                // Data pre-scaled by KS: log2(w) = -(s*s) + lsw : ONE FFMA.
                float2 drf = f2unpack(f2sub(nr, cr[p]));
                float2 dgf = f2unpack(f2sub(ng, cg[p]));
                float2 dbf = f2unpack(f2sub(nb, cb[p]));
                float s0 = fabsf(drf.x) + fabsf(dgf.x);
                float s1 = fabsf(drf.y) + fabsf(dgf.y);
                s0 += fabsf(dbf.x);
                s1 += fabsf(dbf.y);
                u64 w = f2ex2s(fmaf(s0, -s0, lsw), fmaf(s1, -s1, lsw));

                ar[p] = f2fma(w, nr, ar[p]);
                ag[p] = f2fma(w, ng, ag[p]);
                ab[p] = f2fma(w, nb, ab[p]);
                ad[p] = f2add(ad[p], w);
            }
        }
    }

    // ---- write out: 6 contiguous floats per row, 8B-aligned (gx even) ----
    // accumulators hold KS-scaled numerators; fold 1/KS into the reciprocal.
    const int gx = x0 + 2 * threadIdx.x;
#pragma unroll
    for (int p = 0; p < P; ++p) {
        const int gy = y0 + threadIdx.y * P + p;
        float2 R = f2unpack(ar[p]), G = f2unpack(ag[p]);
        float2 B = f2unpack(ab[p]), D = f2unpack(ad[p]);
        float i0 = frcp(D.x) * IKS, i1 = frcp(D.y) * IKS;
        float* o = out + (((size_t)b * IMG_H + gy) * (size_t)IMG_W + gx) * 3;
        ((float2*)o)[0] = make_float2(R.x * i0, G.x * i0);
        ((float2*)o)[1] = make_float2(B.x * i0, R.y * i1);
        ((float2*)o)[2] = make_float2(G.y * i1, B.y * i1);
    }
}

extern "C" void kernel_launch(void* const* d_in, const int* in_sizes, int n_in,
                              void* d_out, int out_size)
{
    (void)in_sizes; (void)n_in; (void)out_size;
    const float* in = (const float*)d_in[0];
    float* out = (float*)d_out;
    cudaFuncSetAttribute(bilateral_kernel,
                         cudaFuncAttributeMaxDynamicSharedMemorySize, SMEM_BYTES);
    dim3 grid(IMG_W / TX, IMG_H / TY, IMG_B);
    dim3 block(BW, BY);
    bilateral_kernel<<<grid, block, SMEM_BYTES>>>(in, out);
}